// round 16
// baseline (speedup 1.0000x reference)
#include <cuda_runtime.h>
#include <cuda_bf16.h>
#include <cstdint>

// DifferentiableNLMS: B=32, T=2000, F=513, L=32, mu=0.1, eps=1e-8
// ONE thread per (b,f). EXACT 8-step block recursion (Gram form):
//   e_k = (y_k - W_bs.Xw_k) - sum_{j<k} c_j G_{jk},  G_{jk} = D_{k-j}(t+j)
// Lag correlations D_0..D_7 (D_0 = norm, EPS-seeded) maintained incrementally
// from X only. Base dots (8x) and the rank-8 W update are fully parallel
// FFMA2 batches; the only serial dependence left is a ~28-FMA scalar triangle.
// Ring = misaligned (P) + aligned (A) packed pair rings, phase-templated.

#define NB 32
#define NT 2000
#define NF 513
#define NL 32
#define MU 0.1f
#define EPSV 1e-8f

#define NSEQ (NB * NF)         // 16416 sequences

typedef unsigned long long u64;

__device__ __forceinline__ u64 ffma2(u64 a, u64 b, u64 c) {
    u64 d; asm("fma.rn.f32x2 %0, %1, %2, %3;" : "=l"(d) : "l"(a), "l"(b), "l"(c));
    return d;
}
__device__ __forceinline__ u64 fadd2(u64 a, u64 b) {
    u64 d; asm("add.rn.f32x2 %0, %1, %2;" : "=l"(d) : "l"(a), "l"(b));
    return d;
}
__device__ __forceinline__ u64 pack2(float lo, float hi) {
    u64 d; asm("mov.b64 %0, {%1, %2};" : "=l"(d) : "f"(lo), "f"(hi));
    return d;
}
__device__ __forceinline__ void unpack2(u64 v, float& lo, float& hi) {
    asm("mov.b64 {%0, %1}, %2;" : "=f"(lo), "=f"(hi) : "l"(v));
}

__device__ __forceinline__ void prefetch8(float (&x)[8], float (&y)[8],
                                          const float* __restrict__ xp,
                                          const float* __restrict__ yp, int t)
{
#pragma unroll
    for (int u = 0; u < 8; u++) {
        x[u] = __ldg(xp + (size_t)(t + u) * NF);
        y[u] = __ldg(yp + (size_t)(t + u) * NF);
    }
}

// M0 = ring phase ((t0/2) & 15): 0, 4, 8, 12.
template <int M0>
__device__ __forceinline__ void run_block8(
    u64 (&W2)[16], u64 (&P)[16], u64 (&A)[16],
    float (&D)[8], float (&xt)[8], float (&tl)[8],
    const float (&xb)[8], const float (&yb)[8],
    float* __restrict__ ep, int t0, bool valid)
{
    // 1) Extract the 8 dropped samples (old aligned pairs, slots M0..M0+3).
    float dr[8];
#pragma unroll
    for (int g = 0; g < 4; g++)
        unpack2(A[(M0 + g) & 15], dr[2 * g], dr[2 * g + 1]);

    // 2) Lag/norm maintenance (X-only) + step sizes + Gram triangle.
    //    xcat[i] = x_{t0-8+i} = (i<8 ? xt[i] : xb[i-8]); dcat analogous with
    //    tl (x_{t0-40..t0-33}) and dr (x_{t0-32..t0-25}).
    float minv[8];
    float gg[7][7];   // gg[l-1][j] = G_{j, j+l}; only j <= 7-l written/read
#pragma unroll
    for (int a = 0; a < 8; a++) {
#pragma unroll
        for (int l = 0; l < 8; l++) {
            float xadd = (a - l >= 0) ? xb[a - l] : xt[8 + a - l];
            float xdrp = (a - l >= 0) ? dr[a - l] : tl[8 + a - l];
            D[l] = fmaf(xadd, xb[a], D[l]);
            D[l] = fmaf(-xdrp, dr[a], D[l]);
            if (l == 0) {
                minv[a] = __fdividef(MU, D[0]);   // EPS folded into D[0] seed
            } else if (a >= l) {
                gg[l - 1][a - l] = D[l];
            }
        }
    }

    // 3) Save old slots needed by the rank-8 update (windows j<6, low taps).
    u64 oP1 = P[(M0 + 1) & 15], oP2 = P[(M0 + 2) & 15], oP3 = P[(M0 + 3) & 15];
    u64 oA1 = A[(M0 + 1) & 15], oA2 = A[(M0 + 2) & 15], oA3 = A[(M0 + 3) & 15];

    // 4) Interleaved inserts + 8 base dots (all against block-start W2; the
    //    dots have no serial dependence - full ILP).
    float d[8];
#pragma unroll
    for (int g = 0; g < 4; g++) {
        const int m = (M0 + g) & 15;
        P[m] = pack2(g ? xb[2 * g - 1] : xt[7], xb[2 * g]);
        A[m] = pack2(xb[2 * g], xb[2 * g + 1]);
        u64 p0 = 0, p1 = 0, q0 = 0, q1 = 0;
#pragma unroll
        for (int i = 0; i < 16; i += 2) {
            p0 = ffma2(W2[i],     P[(m + 1 + i) & 15], p0);
            p1 = ffma2(W2[i + 1], P[(m + 2 + i) & 15], p1);
            q0 = ffma2(W2[i],     A[(m + 1 + i) & 15], q0);
            q1 = ffma2(W2[i + 1], A[(m + 2 + i) & 15], q1);
        }
        u64 sp = fadd2(p0, p1);
        u64 sq = fadd2(q0, q1);
        float plo, phi, qlo, qhi;
        unpack2(sp, plo, phi);
        unpack2(sq, qlo, qhi);
        d[2 * g] = plo + phi;
        d[2 * g + 1] = qlo + qhi;
    }

    // 5) Scalar triangle: the only serial chain (~8 cyc/step).
    float acc[8], c[8];
#pragma unroll
    for (int k = 0; k < 8; k++) acc[k] = yb[k] - d[k];
#pragma unroll
    for (int j = 0; j < 8; j++) {
        c[j] = acc[j] * minv[j];
        if (valid) ep[(size_t)(t0 + j) * NF] = acc[j];   // e_j
#pragma unroll
        for (int k = j + 1; k < 8; k++)
            acc[k] = fmaf(-c[j], gg[k - j - 1][j], acc[k]);
    }

    // 6) Rank-8 W update, per tap in reference order j=0..7.
    //    Window j=2g uses P-slots, j=2g+1 uses A-slots; slots overwritten by
    //    a LATER insert group than the window's own group use saved values.
    u64 cp[8];
#pragma unroll
    for (int j = 0; j < 8; j++) cp[j] = pack2(c[j], c[j]);
#pragma unroll
    for (int i = 0; i < 16; i++) {
        u64 w = W2[i];
#pragma unroll
        for (int g = 0; g < 4; g++) {
            const int rel = (g + 1 + i) & 15;          // slot offset from M0
            const bool useOld = (rel >= 1 && rel <= 3 && rel > g);
            const int mp = (M0 + g + 1 + i) & 15;
            u64 pv = useOld ? (rel == 1 ? oP1 : rel == 2 ? oP2 : oP3) : P[mp];
            u64 av = useOld ? (rel == 1 ? oA1 : rel == 2 ? oA2 : oA3) : A[mp];
            w = ffma2(cp[2 * g], pv, w);
            w = ffma2(cp[2 * g + 1], av, w);
        }
        W2[i] = w;
    }

    // 7) Carries for next block's lag maintenance.
#pragma unroll
    for (int i = 0; i < 8; i++) { tl[i] = dr[i]; xt[i] = xb[i]; }
}

__global__ void __launch_bounds__(128, 1)
nlms_kernel(const float* __restrict__ X, const float* __restrict__ Y,
            const float* __restrict__ Wp, float* __restrict__ out,
            int write_w)
{
    int gtid = blockIdx.x * blockDim.x + threadIdx.x;
    bool valid = (gtid < NSEQ);
    int seq = valid ? gtid : (NSEQ - 1);   // clamp: no divergent exit
    int b = seq / NF;
    int f = seq - b * NF;

    size_t base = (size_t)b * NT * NF + f;
    const float* xp = X + base;
    const float* yp = Y + base;
    float* ep = out + base;                // E_hat_mag at offset 0

    u64 W2[16], P[16], A[16];
#pragma unroll
    for (int i = 0; i < 16; i++) {
        float w0 = Wp[((size_t)b * NL + 2 * i) * NF + f];
        float w1 = Wp[((size_t)b * NL + 2 * i + 1) * NF + f];
        W2[i] = pack2(w0, w1);
        P[i] = 0;                          // zero pad: window starts empty
        A[i] = 0;
    }
    float D[8];
#pragma unroll
    for (int l = 0; l < 8; l++) D[l] = 0.f;
    D[0] = EPSV;                           // EPS inside the norm lag
    float xt[8], tl[8];
#pragma unroll
    for (int i = 0; i < 8; i++) { xt[i] = 0.f; tl[i] = 0.f; }

    float xA[8], yA[8], xB[8], yB[8];
    prefetch8(xA, yA, xp, yp, 0);

    int t0 = 0;
    // 250 blocks of 8 steps; phase cycles 0,4,8,12; buffers alternate A,B.
#pragma unroll 1
    for (int mm = 0; mm < 62; mm++) {      // blocks 0..247
        prefetch8(xB, yB, xp, yp, t0 + 8);
        run_block8<0>(W2, P, A, D, xt, tl, xA, yA, ep, t0, valid);
        t0 += 8;
        prefetch8(xA, yA, xp, yp, t0 + 8);
        run_block8<4>(W2, P, A, D, xt, tl, xB, yB, ep, t0, valid);
        t0 += 8;
        prefetch8(xB, yB, xp, yp, t0 + 8);
        run_block8<8>(W2, P, A, D, xt, tl, xA, yA, ep, t0, valid);
        t0 += 8;
        prefetch8(xA, yA, xp, yp, t0 + 8);  // mm=61 loads block 248
        run_block8<12>(W2, P, A, D, xt, tl, xB, yB, ep, t0, valid);
        t0 += 8;
    }
    // blocks 248 (phase 0, buf A) and 249 (phase 4, buf B)
    prefetch8(xB, yB, xp, yp, t0 + 8);
    run_block8<0>(W2, P, A, D, xt, tl, xA, yA, ep, t0, valid);
    t0 += 8;
    run_block8<4>(W2, P, A, D, xt, tl, xB, yB, ep, t0, valid);

    if (write_w) {
        float* wf = out + (size_t)NB * NT * NF;  // W_final after E
#pragma unroll
        for (int i = 0; i < 16; i++) {
            float w0, w1;
            unpack2(W2[i], w0, w1);
            if (valid) {
                wf[((size_t)b * NL + 2 * i) * NF + f] = w0;
                wf[((size_t)b * NL + 2 * i + 1) * NF + f] = w1;
            }
        }
    }
}

extern "C" void kernel_launch(void* const* d_in, const int* in_sizes, int n_in,
                              void* d_out, int out_size)
{
    const float* X  = (const float*)d_in[0];  // X_hat_mag [B,T,F]
    const float* Y  = (const float*)d_in[1];  // Y_mag     [B,T,F]
    const float* Wp = (const float*)d_in[2];  // W_prev    [B,L,F]
    float* out = (float*)d_out;

    long long need = (long long)NB * NT * NF + (long long)NB * NL * NF;
    int write_w = ((long long)out_size >= need) ? 1 : 0;

    // 16416 sequences -> 129 blocks of 128 (96 clamped duplicates).
    // 1 block/SM, 1 warp/SMSP; warp loads 32 consecutive f (128B lines).
    nlms_kernel<<<129, 128>>>(X, Y, Wp, out, write_w);
}

// round 17
// speedup vs baseline: 1.4898x; 1.4898x over previous
#include <cuda_runtime.h>
#include <cuda_bf16.h>
#include <cstdint>

// DifferentiableNLMS: B=32, T=2000, F=513, L=32, mu=0.1, eps=1e-8
// R13 core (one thread per (b,f), no shuffles, packed f32x2, 16-pair ring,
// 2-step lookahead, packed (S|CC) prologue, EPS folded into seed) with ONE
// change: grid padded to 160 (>=148) with immediate-exit padding blocks, to
// dodge the low-grid large-body issue throttle (pSmIssueThrottleCtrl) that
// engages below grid 148.

#define NB 32
#define NT 2000
#define NF 513
#define NL 32
#define MU 0.1f
#define EPSV 1e-8f

#define NSEQ (NB * NF)         // 16416 sequences
#define NSTEP 16
#define NPB 8
#define NDBL 62                // 62*2+1 = 125 blocks of 16 steps
#define NWORK 129              // active blocks (129*128 >= 16416)

typedef unsigned long long u64;

__device__ __forceinline__ u64 ffma2(u64 a, u64 b, u64 c) {
    u64 d; asm("fma.rn.f32x2 %0, %1, %2, %3;" : "=l"(d) : "l"(a), "l"(b), "l"(c));
    return d;
}
__device__ __forceinline__ u64 fadd2(u64 a, u64 b) {
    u64 d; asm("add.rn.f32x2 %0, %1, %2;" : "=l"(d) : "l"(a), "l"(b));
    return d;
}
__device__ __forceinline__ u64 pack2(float lo, float hi) {
    u64 d; asm("mov.b64 %0, {%1, %2};" : "=l"(d) : "f"(lo), "f"(hi));
    return d;
}
__device__ __forceinline__ void unpack2(u64 v, float& lo, float& hi) {
    asm("mov.b64 {%0, %1}, %2;" : "=f"(lo), "=f"(hi) : "l"(v));
}
__device__ __forceinline__ float negf(float x) {   // sign flip on alu pipe
    return __int_as_float(__float_as_int(x) ^ 0x80000000);
}

__device__ __forceinline__ void prefetch(float (&x)[NSTEP], float (&y)[NSTEP],
                                         const float* __restrict__ xp,
                                         const float* __restrict__ yp, int t)
{
#pragma unroll
    for (int u = 0; u < NSTEP; u++) {
        x[u] = __ldg(xp + (size_t)(t + u) * NF);
        y[u] = __ldg(yp + (size_t)(t + u) * NF);
    }
}

// M0 = ring phase ((t0/2) mod 16): 0 or 8.
template <int M0>
__device__ __forceinline__ void run_block(
    u64 (&W2)[16], u64 (&P)[16], u64 (&Q)[16],
    u64& SC, float& xlast,
    const float (&xb)[NSTEP], const float (&yb)[NSTEP],
    float* __restrict__ ep, int t0, bool valid)
{
    float minv[NSTEP];
    float ccs[NPB];
    float xm1_0 = xlast;

    // ---- Prologue: packed (S | CC) incremental chain, X-only ----
    // lo(SC) = full-window norm + EPS (seeded); hi(SC) = lag-1 cross-corr.
    // Drops read OLD ring slots (32 samples back) before any insertion.
    {
        u64 sc = SC;
        float s0a[NPB], s1a[NPB], cca[NPB];
#pragma unroll
        for (int p = 0; p < NPB; p++) {
            const int m = (M0 + p) & 15;
            float a, b, bq, cq;
            unpack2(P[m], a, b);   // (x_{t-33}, x_{t-32})
            unpack2(Q[m], bq, cq); // (x_{t-32}, x_{t-31})
            float xm1 = p ? xb[2 * p - 1] : xm1_0;
            float x0 = xb[2 * p], x1 = xb[2 * p + 1];
            // S += x0^2 ; CC += xm1*x0
            sc = ffma2(pack2(x0, xm1), pack2(x0, x0), sc);
            // S -= b^2  ; CC -= a*b
            sc = ffma2(pack2(negf(b), negf(a)), pack2(b, b), sc);
            { float slo, shi; unpack2(sc, slo, shi); s0a[p] = slo; }
            // S += x1^2 ; CC += x0*x1
            sc = ffma2(pack2(x1, x0), pack2(x1, x1), sc);
            // S -= cq^2 ; CC -= bq*cq
            sc = ffma2(pack2(negf(cq), negf(bq)), pack2(cq, cq), sc);
            { float slo, shi; unpack2(sc, slo, shi); s1a[p] = slo; cca[p] = shi; }
        }
        SC = sc;
#pragma unroll
        for (int p = 0; p < NPB; p++) {
            minv[2 * p]     = __fdividef(MU, s0a[p]);  // EPS already inside S
            minv[2 * p + 1] = __fdividef(MU, s1a[p]);
            ccs[p] = cca[p];
        }
    }
    xlast = xb[NSTEP - 1];

    // ---- Serial recursion: 2 steps per iteration, no cross-lane traffic ----
#pragma unroll
    for (int p = 0; p < NPB; p++) {
        const int m = (M0 + p) & 15;
        float xm1 = p ? xb[2 * p - 1] : xm1_0;
        float x0 = xb[2 * p], x1 = xb[2 * p + 1];
        P[m] = pack2(xm1, x0);  // slot holds (x_{t-1}, x_t)
        Q[m] = pack2(x0, x1);   // slot holds (x_t, x_{t+1})

        // Full 32-tap dots, both phases, 8 accumulators.
        u64 a0 = 0, a1 = 0, a2 = 0, a3 = 0;
        u64 b0 = 0, b1 = 0, b2 = 0, b3 = 0;
#pragma unroll
        for (int i = 0; i < 16; i += 4) {
            a0 = ffma2(W2[i + 0], P[(m + 1 + i) & 15], a0);
            a1 = ffma2(W2[i + 1], P[(m + 2 + i) & 15], a1);
            a2 = ffma2(W2[i + 2], P[(m + 3 + i) & 15], a2);
            a3 = ffma2(W2[i + 3], P[(m + 4 + i) & 15], a3);
            b0 = ffma2(W2[i + 0], Q[(m + 1 + i) & 15], b0);
            b1 = ffma2(W2[i + 1], Q[(m + 2 + i) & 15], b1);
            b2 = ffma2(W2[i + 2], Q[(m + 3 + i) & 15], b2);
            b3 = ffma2(W2[i + 3], Q[(m + 4 + i) & 15], b3);
        }
        u64 ap = fadd2(fadd2(a0, a1), fadd2(a2, a3));
        u64 aq = fadd2(fadd2(b0, b1), fadd2(b2, b3));
        float plo, phi, qlo, qhi;
        unpack2(ap, plo, phi);
        unpack2(aq, qlo, qhi);
        float pt = plo + phi;
        float qt = qlo + qhi;

        float e0 = yb[2 * p] - pt;
        float c0 = e0 * minv[2 * p];
        float e1 = fmaf(-c0, ccs[p], yb[2 * p + 1] - qt);
        float c1 = e1 * minv[2 * p + 1];

        if (valid) {
            ep[(size_t)(t0 + 2 * p) * NF] = e0;
            ep[(size_t)(t0 + 2 * p + 1) * NF] = e1;
        }

        u64 c0p = pack2(c0, c0);
        u64 c1p = pack2(c1, c1);
#pragma unroll
        for (int i = 0; i < 16; i++) {
            W2[i] = ffma2(c1p, Q[(m + 1 + i) & 15],
                          ffma2(c0p, P[(m + 1 + i) & 15], W2[i]));
        }
    }
}

__global__ void __launch_bounds__(128, 1)
nlms_kernel(const float* __restrict__ X, const float* __restrict__ Y,
            const float* __restrict__ Wp, float* __restrict__ out,
            int write_w)
{
    // Padding blocks (>=NWORK) exit immediately - they exist only to push the
    // launch grid above the 148-block issue-throttle threshold.
    if (blockIdx.x >= NWORK) return;

    int gtid = blockIdx.x * blockDim.x + threadIdx.x;
    bool valid = (gtid < NSEQ);
    int seq = valid ? gtid : (NSEQ - 1);   // clamp: no divergent exit
    int b = seq / NF;
    int f = seq - b * NF;

    size_t base = (size_t)b * NT * NF + f;
    const float* xp = X + base;
    const float* yp = Y + base;
    float* ep = out + base;                // E_hat_mag at offset 0

    u64 W2[16], P[16], Q[16];
#pragma unroll
    for (int i = 0; i < 16; i++) {
        float w0 = Wp[((size_t)b * NL + 2 * i) * NF + f];
        float w1 = Wp[((size_t)b * NL + 2 * i + 1) * NF + f];
        W2[i] = pack2(w0, w1);
        P[i] = 0;                          // zero pad: window starts empty
        Q[i] = 0;
    }
    // lo = norm (+EPS seeded), hi = lag-1 cross-correlation.
    u64 SC = pack2(EPSV, 0.f);
    float xlast = 0.f;

    float xA[NSTEP], yA[NSTEP], xB[NSTEP], yB[NSTEP];
    prefetch(xA, yA, xp, yp, 0);

    int t0 = 0;
#pragma unroll 1
    for (int dd = 0; dd < NDBL; dd++) {
        prefetch(xB, yB, xp, yp, t0 + NSTEP);
        run_block<0>(W2, P, Q, SC, xlast, xA, yA, ep, t0, valid);
        t0 += NSTEP;
        prefetch(xA, yA, xp, yp, t0 + NSTEP);  // last iter loads block 124
        run_block<8>(W2, P, Q, SC, xlast, xB, yB, ep, t0, valid);
        t0 += NSTEP;
    }
    run_block<0>(W2, P, Q, SC, xlast, xA, yA, ep, t0, valid);  // t0 = 1984

    if (write_w) {
        float* wf = out + (size_t)NB * NT * NF;  // W_final after E
#pragma unroll
        for (int i = 0; i < 16; i++) {
            float w0, w1;
            unpack2(W2[i], w0, w1);
            if (valid) {
                wf[((size_t)b * NL + 2 * i) * NF + f] = w0;
                wf[((size_t)b * NL + 2 * i + 1) * NF + f] = w1;
            }
        }
    }
}

extern "C" void kernel_launch(void* const* d_in, const int* in_sizes, int n_in,
                              void* d_out, int out_size)
{
    const float* X  = (const float*)d_in[0];  // X_hat_mag [B,T,F]
    const float* Y  = (const float*)d_in[1];  // Y_mag     [B,T,F]
    const float* Wp = (const float*)d_in[2];  // W_prev    [B,L,F]
    float* out = (float*)d_out;

    long long need = (long long)NB * NT * NF + (long long)NB * NL * NF;
    int write_w = ((long long)out_size >= need) ? 1 : 0;

    // 129 working blocks + 31 immediate-exit padding blocks = grid 160 >= 148
    // (issue-throttle threshold). 1 block/SM, 1 warp/SMSP on active SMs.
    nlms_kernel<<<160, 128>>>(X, Y, Wp, out, write_w);
}